// round 1
// baseline (speedup 1.0000x reference)
#include <cuda_runtime.h>
#include <cstdint>
#include <cstddef>

// ---------------------------------------------------------------------------
// DeepCausalModel: trunk MLP (512->2048->2048->512, ReLU after every linear),
// dense per-treatment experts (512->1024->512, ReLU), treatment-gathered head,
// t_out = softmax over size-1 axis == 1.0.
// TF32 tensor-core GEMMs (mma.sync m16n8k8) with RNA pre-rounding of inputs.
// ---------------------------------------------------------------------------

#define NROWS 65536

// ---- scratch layout (element offsets into g_scratch, fp32) ----
constexpr size_t SZ_XR   = (size_t)NROWS * 512;          // rounded X
constexpr size_t OFF_XR  = 0;
constexpr size_t OFF_WX0 = OFF_XR  + SZ_XR;              // 512*2048
constexpr size_t OFF_WX1 = OFF_WX0 + (size_t)512 * 2048; // 2048*2048
constexpr size_t OFF_WX2 = OFF_WX1 + (size_t)2048 * 2048;// 2048*512
constexpr size_t OFF_WY0 = OFF_WX2 + (size_t)2048 * 512; // 2*512*1024
constexpr size_t OFF_WY1 = OFF_WY0 + (size_t)2 * 512 * 1024; // 2*1024*512
constexpr size_t OFF_H0  = OFF_WY1 + (size_t)2 * 1024 * 512; // N*2048
constexpr size_t OFF_H1  = OFF_H0  + (size_t)NROWS * 2048;   // N*2048
constexpr size_t OFF_XER = OFF_H1  + (size_t)NROWS * 2048;   // N*512
constexpr size_t SCR_TOTAL = OFF_XER + (size_t)NROWS * 512;
// recycled regions (H0/H1 dead once x_emb is produced)
constexpr size_t OFF_G0A = OFF_H0;
constexpr size_t OFF_G0B = OFF_H0 + (size_t)NROWS * 1024;
constexpr size_t OFF_G1A = OFF_H1;
constexpr size_t OFF_G1B = OFF_H1 + (size_t)NROWS * 512;

__device__ float g_scratch[SCR_TOTAL];

// ---------------------------------------------------------------------------
__device__ __forceinline__ float rna_tf32(float x) {
    unsigned u;
    asm("cvt.rna.tf32.f32 %0, %1;" : "=r"(u) : "f"(x));
    return __uint_as_float(u);
}

__global__ void round4_kernel(const float4* __restrict__ in,
                              float4* __restrict__ out, int n4) {
    int i = blockIdx.x * blockDim.x + threadIdx.x;
    if (i < n4) {
        float4 v = in[i];
        v.x = rna_tf32(v.x); v.y = rna_tf32(v.y);
        v.z = rna_tf32(v.z); v.w = rna_tf32(v.w);
        out[i] = v;
    }
}

// ---------------------------------------------------------------------------
// TF32 GEMM: C = relu(A[M,K] @ B[K,N] + bias[N]);  all of M%128,N%128,K%32 == 0
// ---------------------------------------------------------------------------
constexpr int BM = 128, BN = 128, BK = 32;
constexpr int SA = 36;   // A smem row stride (floats), conflict-free frag loads
constexpr int SB = 136;  // B smem row stride
constexpr int ASZ = BM * SA;
constexpr int BSZ = BK * SB;
constexpr int GEMM_SMEM = (2 * ASZ + 2 * BSZ) * 4;  // 71680 B

__device__ __forceinline__ void cp16(float* dst, const float* src) {
    unsigned d = (unsigned)__cvta_generic_to_shared(dst);
    asm volatile("cp.async.cg.shared.global [%0], [%1], 16;\n" :: "r"(d), "l"(src));
}
__device__ __forceinline__ void cp_commit() {
    asm volatile("cp.async.commit_group;\n" ::);
}
template <int NN>
__device__ __forceinline__ void cp_wait() {
    asm volatile("cp.async.wait_group %0;\n" :: "n"(NN));
}

__device__ __forceinline__ void mma_tf32(float* d, const unsigned* a, const unsigned* b) {
    asm volatile(
        "mma.sync.aligned.m16n8k8.row.col.f32.tf32.tf32.f32 "
        "{%0,%1,%2,%3}, {%4,%5,%6,%7}, {%8,%9}, {%0,%1,%2,%3};\n"
        : "+f"(d[0]), "+f"(d[1]), "+f"(d[2]), "+f"(d[3])
        : "r"(a[0]), "r"(a[1]), "r"(a[2]), "r"(a[3]), "r"(b[0]), "r"(b[1]));
}

template <bool ROUND, bool DUAL>
__global__ void __launch_bounds__(256, 2)
gemm_tf32(const float* __restrict__ A, const float* __restrict__ B,
          const float* __restrict__ bias, float* __restrict__ C,
          float* __restrict__ C2, int M, int N, int K) {
    extern __shared__ float smem[];
    float* sA = smem;
    float* sB = smem + 2 * ASZ;

    const int tid  = threadIdx.x;
    const int lane = tid & 31;
    const int warp = tid >> 5;
    const int wm   = warp & 1;   // 2 warps along M (64 rows each)
    const int wn   = warp >> 1;  // 4 warps along N (32 cols each)
    const int m0   = blockIdx.y * BM;
    const int n0   = blockIdx.x * BN;

    const float* Ab = A + (size_t)m0 * K;
    const float* Bb = B + n0;

    float acc[4][4][4];
#pragma unroll
    for (int i = 0; i < 4; i++)
#pragma unroll
        for (int j = 0; j < 4; j++)
#pragma unroll
            for (int q = 0; q < 4; q++) acc[i][j][q] = 0.f;

    auto load_tiles = [&](int kt, int b) {
        const int k0 = kt * BK;
#pragma unroll
        for (int i = 0; i < 4; i++) {  // A: 128x32 floats, 16B chunks
            int c = tid + i * 256;
            int r = c >> 3, kc = (c & 7) * 4;
            cp16(sA + b * ASZ + r * SA + kc, Ab + (size_t)r * K + k0 + kc);
        }
#pragma unroll
        for (int i = 0; i < 4; i++) {  // B: 32x128 floats
            int c = tid + i * 256;
            int kk = c >> 5, nc = (c & 31) * 4;
            cp16(sB + b * BSZ + kk * SB + nc, Bb + (size_t)(k0 + kk) * N + nc);
        }
        cp_commit();
    };

    load_tiles(0, 0);
    const int nk = K / BK;
    int buf = 0;
    for (int kt = 0; kt < nk; ++kt) {
        if (kt + 1 < nk) { load_tiles(kt + 1, buf ^ 1); cp_wait<1>(); }
        else             { cp_wait<0>(); }
        __syncthreads();

        const float* as = sA + buf * ASZ;
        const float* bs = sB + buf * BSZ;
#pragma unroll
        for (int ks = 0; ks < BK / 8; ++ks) {
            unsigned af[4][4], bf[4][2];
            const int kA = ks * 8 + (lane & 3);
#pragma unroll
            for (int mt = 0; mt < 4; ++mt) {
                const int r = wm * 64 + mt * 16 + (lane >> 2);
                af[mt][0] = __float_as_uint(as[r * SA + kA]);
                af[mt][1] = __float_as_uint(as[(r + 8) * SA + kA]);
                af[mt][2] = __float_as_uint(as[r * SA + kA + 4]);
                af[mt][3] = __float_as_uint(as[(r + 8) * SA + kA + 4]);
            }
#pragma unroll
            for (int nt = 0; nt < 4; ++nt) {
                const int n_ = wn * 32 + nt * 8 + (lane >> 2);
                bf[nt][0] = __float_as_uint(bs[kA * SB + n_]);
                bf[nt][1] = __float_as_uint(bs[(kA + 4) * SB + n_]);
            }
#pragma unroll
            for (int mt = 0; mt < 4; ++mt)
#pragma unroll
                for (int nt = 0; nt < 4; ++nt)
                    mma_tf32(acc[mt][nt], af[mt], bf[nt]);
        }
        __syncthreads();
        buf ^= 1;
    }

    // epilogue: +bias, ReLU, optional RNA-tf32 rounding, optional dual store
#pragma unroll
    for (int nt = 0; nt < 4; ++nt) {
        const int col = n0 + wn * 32 + nt * 8 + 2 * (lane & 3);
        const float b0v = bias[col], b1v = bias[col + 1];
#pragma unroll
        for (int mt = 0; mt < 4; ++mt) {
            const int row = m0 + wm * 64 + mt * 16 + (lane >> 2);
            float v0 = fmaxf(acc[mt][nt][0] + b0v, 0.f);
            float v1 = fmaxf(acc[mt][nt][1] + b1v, 0.f);
            float v2 = fmaxf(acc[mt][nt][2] + b0v, 0.f);
            float v3 = fmaxf(acc[mt][nt][3] + b1v, 0.f);
            const size_t o0 = (size_t)row * N + col;
            const size_t o1 = (size_t)(row + 8) * N + col;
            if (DUAL) {  // unrounded copy (x_emb output)
                *(float2*)(C2 + o0) = make_float2(v0, v1);
                *(float2*)(C2 + o1) = make_float2(v2, v3);
            }
            if (ROUND) {
                v0 = rna_tf32(v0); v1 = rna_tf32(v1);
                v2 = rna_tf32(v2); v3 = rna_tf32(v3);
            }
            *(float2*)(C + o0) = make_float2(v0, v1);
            *(float2*)(C + o1) = make_float2(v2, v3);
        }
    }
}

// ---------------------------------------------------------------------------
// Head: y[n] = dot(G1[t[n]][n,:512], Wo[t[n]]) + bo[t[n]];  t_out[n] = 1.0
// Detects int64-vs-int32 treatment buffer (odd 32-bit words all zero => i64).
// ---------------------------------------------------------------------------
__global__ void head_kernel(const int* __restrict__ traw,
                            const float* __restrict__ g1a,
                            const float* __restrict__ g1b,
                            const float* __restrict__ Wo,
                            const float* __restrict__ bo,
                            float* __restrict__ y, float* __restrict__ tout) {
    __shared__ int s_is64;
    if (threadIdx.x == 0) {
        int a = 0;
#pragma unroll
        for (int i = 1; i < 64; i += 2) a |= traw[i];
        s_is64 = (a == 0) ? 1 : 0;
    }
    __syncthreads();
    const int lane = threadIdx.x & 31;
    const int row  = blockIdx.x * 8 + (threadIdx.x >> 5);
    const int t    = s_is64 ? traw[2 * row] : traw[row];
    const float* g = (t ? g1b : g1a) + (size_t)row * 512;
    const float* w = Wo + t * 512;
    float s = 0.f;
#pragma unroll
    for (int j = 0; j < 4; j++) {
        float4 gv = *(const float4*)(g + j * 128 + lane * 4);
        float4 wv = *(const float4*)(w + j * 128 + lane * 4);
        s += gv.x * wv.x + gv.y * wv.y + gv.z * wv.z + gv.w * wv.w;
    }
#pragma unroll
    for (int o = 16; o > 0; o >>= 1) s += __shfl_xor_sync(0xffffffffu, s, o);
    if (lane == 0) {
        y[row]    = s + bo[t];
        tout[row] = 1.0f;  // softmax over a size-1 axis
    }
}

// ---------------------------------------------------------------------------
extern "C" void kernel_launch(void* const* d_in, const int* in_sizes, int n_in,
                              void* d_out, int out_size) {
    const float* x   = (const float*)d_in[0];
    const int*   tr  = (const int*)  d_in[1];
    const float* Wx0 = (const float*)d_in[2];
    const float* bx0 = (const float*)d_in[3];
    const float* Wx1 = (const float*)d_in[4];
    const float* bx1 = (const float*)d_in[5];
    const float* Wx2 = (const float*)d_in[6];
    const float* bx2 = (const float*)d_in[7];
    const float* Wy0 = (const float*)d_in[8];
    const float* by0 = (const float*)d_in[9];
    const float* Wy1 = (const float*)d_in[10];
    const float* by1 = (const float*)d_in[11];
    const float* Wo  = (const float*)d_in[12];
    const float* bo  = (const float*)d_in[13];
    // d_in[14]/d_in[15] (Wt, bt) are dead: softmax over size-1 axis == 1.

    float* out  = (float*)d_out;
    float* y    = out;                                  // [N]
    float* xemb = out + NROWS;                          // [N,512]
    float* tout = out + NROWS + (size_t)NROWS * 512;    // [N]

    float* scr = nullptr;
    cudaGetSymbolAddress((void**)&scr, g_scratch);

    float* Xr   = scr + OFF_XR;
    float* WX0r = scr + OFF_WX0;
    float* WX1r = scr + OFF_WX1;
    float* WX2r = scr + OFF_WX2;
    float* WY0r = scr + OFF_WY0;
    float* WY1r = scr + OFF_WY1;
    float* H0   = scr + OFF_H0;
    float* H1   = scr + OFF_H1;
    float* XEr  = scr + OFF_XER;
    float* G0a  = scr + OFF_G0A;
    float* G0b  = scr + OFF_G0B;
    float* G1a  = scr + OFF_G1A;
    float* G1b  = scr + OFF_G1B;

    cudaFuncSetAttribute(gemm_tf32<true,  false>,
                         cudaFuncAttributeMaxDynamicSharedMemorySize, GEMM_SMEM);
    cudaFuncSetAttribute(gemm_tf32<true,  true>,
                         cudaFuncAttributeMaxDynamicSharedMemorySize, GEMM_SMEM);
    cudaFuncSetAttribute(gemm_tf32<false, false>,
                         cudaFuncAttributeMaxDynamicSharedMemorySize, GEMM_SMEM);

    auto roundN = [&](const float* src, float* dst, size_t n) {
        int n4 = (int)(n / 4);
        round4_kernel<<<(n4 + 255) / 256, 256>>>((const float4*)src, (float4*)dst, n4);
    };

    // Pre-round inputs/weights to tf32 (RNA) so the GEMM mainloop is cvt-free
    roundN(x,   Xr,   (size_t)NROWS * 512);
    roundN(Wx0, WX0r, (size_t)512 * 2048);
    roundN(Wx1, WX1r, (size_t)2048 * 2048);
    roundN(Wx2, WX2r, (size_t)2048 * 512);
    roundN(Wy0, WY0r, (size_t)2 * 512 * 1024);
    roundN(Wy1, WY1r, (size_t)2 * 1024 * 512);

    const dim3 blk(256);
    const int MT = NROWS / 128;  // 512 m-tiles

    // trunk
    gemm_tf32<true, false><<<dim3(2048 / 128, MT), blk, GEMM_SMEM>>>(
        Xr, WX0r, bx0, H0, nullptr, NROWS, 2048, 512);
    gemm_tf32<true, false><<<dim3(2048 / 128, MT), blk, GEMM_SMEM>>>(
        H0, WX1r, bx1, H1, nullptr, NROWS, 2048, 2048);
    gemm_tf32<true, true><<<dim3(512 / 128, MT), blk, GEMM_SMEM>>>(
        H1, WX2r, bx2, XEr, xemb, NROWS, 512, 2048);  // rounded + x_emb output

    // experts (dense over T=2)
    gemm_tf32<true, false><<<dim3(1024 / 128, MT), blk, GEMM_SMEM>>>(
        XEr, WY0r, by0, G0a, nullptr, NROWS, 1024, 512);
    gemm_tf32<true, false><<<dim3(1024 / 128, MT), blk, GEMM_SMEM>>>(
        XEr, WY0r + (size_t)512 * 1024, by0 + 1024, G0b, nullptr, NROWS, 1024, 512);
    gemm_tf32<false, false><<<dim3(512 / 128, MT), blk, GEMM_SMEM>>>(
        G0a, WY1r, by1, G1a, nullptr, NROWS, 512, 1024);
    gemm_tf32<false, false><<<dim3(512 / 128, MT), blk, GEMM_SMEM>>>(
        G0b, WY1r + (size_t)1024 * 512, by1 + 512, G1b, nullptr, NROWS, 512, 1024);

    // gathered head + t_out
    head_kernel<<<NROWS / 8, 256>>>(tr, G1a, G1b, Wo, bo, y, tout);
}

// round 3
// speedup vs baseline: 1.0955x; 1.0955x over previous
#include <cuda_runtime.h>
#include <cstdint>
#include <cstddef>

// ---------------------------------------------------------------------------
// DeepCausalModel, legacy-tensor-core path (tcgen05 not available: harness
// compiles via compute_103 PTX which rejects sm_103a-gated features).
// TF32 mma.sync m16n8k8, CTA tile 256x128, warp tile 64x64 (smem-byte/MAC
// = 0.125), double-buffered cp.async. Experts run gathered-by-treatment
// (device-side partition, compact rows, scatter at head).
// ---------------------------------------------------------------------------

#define NROWS 65536

// ---- fp32 scratch ----
constexpr size_t OFF_XR  = 0;                               // [N,512] rounded X
constexpr size_t OFF_WX0 = OFF_XR  + (size_t)NROWS * 512;   // [2048,512] (transposed)
constexpr size_t OFF_WX1 = OFF_WX0 + (size_t)512 * 2048;    // [2048,2048]
constexpr size_t OFF_WX2 = OFF_WX1 + (size_t)2048 * 2048;   // [512,2048]
constexpr size_t OFF_WY0 = OFF_WX2 + (size_t)2048 * 512;    // 2x [1024,512]
constexpr size_t OFF_WY1 = OFF_WY0 + (size_t)2 * 512 * 1024;// 2x [512,1024]
constexpr size_t OFF_H0  = OFF_WY1 + (size_t)2 * 1024 * 512;// [N,2048]
constexpr size_t OFF_H1  = OFF_H0  + (size_t)NROWS * 2048;  // [N,2048]
constexpr size_t OFF_XER = OFF_H1  + (size_t)NROWS * 2048;  // [N,512]
constexpr size_t SCR_TOTAL = OFF_XER + (size_t)NROWS * 512;
// recycled regions (worst-case per-expert compact buffers)
constexpr size_t OFF_G0A = OFF_H0;
constexpr size_t OFF_G0B = OFF_H0 + (size_t)NROWS * 1024;
constexpr size_t OFF_G1A = OFF_H1;
constexpr size_t OFF_G1B = OFF_H1 + (size_t)NROWS * 512;

__device__ float g_scratch[SCR_TOTAL];
__device__ int   g_idx0[NROWS];
__device__ int   g_idx1[NROWS];
__device__ int   g_meta[8];  // [0]=cnt0 [1]=pad0 [2]=cnt1 [3]=pad1 [4],[5]=cursors

// ---------------------------------------------------------------------------
__device__ __forceinline__ float rna_tf32(float x) {
    unsigned u;
    asm("cvt.rna.tf32.f32 %0, %1;" : "=r"(u) : "f"(x));
    return __uint_as_float(u);
}

__global__ void round4_kernel(const float4* __restrict__ in,
                              float4* __restrict__ out, int n4) {
    int i = blockIdx.x * blockDim.x + threadIdx.x;
    if (i < n4) {
        float4 v = in[i];
        v.x = rna_tf32(v.x); v.y = rna_tf32(v.y);
        v.z = rna_tf32(v.z); v.w = rna_tf32(v.w);
        out[i] = v;
    }
}

// transpose [K,N] row-major -> [N,K] row-major, RNA-tf32 rounded
__global__ void transpose_round(const float* __restrict__ W,
                                float* __restrict__ WT, int K, int N) {
    __shared__ float t[32][33];
    const int bx = blockIdx.x * 32, by = blockIdx.y * 32;
    const int x = threadIdx.x, y = threadIdx.y;
#pragma unroll
    for (int i = 0; i < 32; i += 8)
        t[y + i][x] = W[(size_t)(by + y + i) * N + bx + x];
    __syncthreads();
#pragma unroll
    for (int i = 0; i < 32; i += 8)
        WT[(size_t)(bx + y + i) * K + by + x] = rna_tf32(t[x][y + i]);
}

// ---------------------------------------------------------------------------
// partition rows by treatment (handles int64-or-int32 treatment buffer)
// ---------------------------------------------------------------------------
__device__ __forceinline__ int detect64_load(const int* tr, int row, int is64) {
    return is64 ? tr[2 * row] : tr[row];
}
__device__ __forceinline__ int detect64(const int* tr) {
    int a = 0;
#pragma unroll
    for (int i = 1; i < 64; i += 2) a |= tr[i];
    return (a == 0) ? 1 : 0;
}

__global__ void zero_meta_kernel() {
    if (threadIdx.x < 8) g_meta[threadIdx.x] = 0;
}

__global__ void count_kernel(const int* __restrict__ tr) {
    __shared__ int s64;
    if (threadIdx.x == 0) s64 = detect64(tr);
    __syncthreads();
    const int row = blockIdx.x * 256 + threadIdx.x;
    const int t = detect64_load(tr, row, s64);
    unsigned m0 = __ballot_sync(0xffffffffu, t == 0);
    if ((threadIdx.x & 31) == 0) atomicAdd(&g_meta[0], __popc(m0));
}

__global__ void scatter_kernel(const int* __restrict__ tr) {
    __shared__ int s64;
    if (threadIdx.x == 0) s64 = detect64(tr);
    __syncthreads();
    const int row = blockIdx.x * 256 + threadIdx.x;
    const int t = detect64_load(tr, row, s64);
    const unsigned full = 0xffffffffu;
    const unsigned mask0 = __ballot_sync(full, t == 0);
    const int c0 = __popc(mask0);
    int b0 = 0, b1 = 0;
    if ((threadIdx.x & 31) == 0) {
        b0 = atomicAdd(&g_meta[4], c0);
        b1 = atomicAdd(&g_meta[5], 32 - c0);
    }
    b0 = __shfl_sync(full, b0, 0);
    b1 = __shfl_sync(full, b1, 0);
    const unsigned lt = (1u << (threadIdx.x & 31)) - 1u;
    if (t == 0) g_idx0[b0 + __popc(mask0 & lt)] = row;
    else        g_idx1[b1 + __popc((~mask0) & lt)] = row;
}

__global__ void pad_kernel() {
    const int cnt0 = g_meta[0];
    const int cnt1 = NROWS - cnt0;
    const int p0 = (cnt0 + 255) & ~255;
    const int p1 = (cnt1 + 255) & ~255;
    if (threadIdx.x == 0) { g_meta[1] = p0; g_meta[2] = cnt1; g_meta[3] = p1; }
    const int f0 = (cnt0 > 0) ? g_idx0[0] : 0;
    const int f1 = (cnt1 > 0) ? g_idx1[0] : 0;
    for (int i = cnt0 + threadIdx.x; i < p0; i += 256) g_idx0[i] = f0;
    for (int i = cnt1 + threadIdx.x; i < p1; i += 256) g_idx1[i] = f1;
}

// ---------------------------------------------------------------------------
// TF32 GEMM: C[M,N] = relu(A[M,K] @ BT[N,K]^T + bias)
// CTA 256x128, warp 64x64, BK=32. IDX: gather A rows via idx. DYN: early-exit
// CTAs past device-side padded row count (cap).
// ---------------------------------------------------------------------------
constexpr int SAF = 36;                       // smem row stride (floats)
constexpr int A_FLOATS = 256 * SAF;           // 9216
constexpr int STG_FLOATS = A_FLOATS + 128 * SAF;  // 13824
constexpr int STG_BYTES = STG_FLOATS * 4;     // 55296
constexpr int GEMM_SMEM = 2 * STG_BYTES;      // 110592

__device__ __forceinline__ void cp16s(uint32_t daddr, const float* src) {
    asm volatile("cp.async.cg.shared.global [%0], [%1], 16;" :: "r"(daddr), "l"(src));
}
__device__ __forceinline__ void cp_commit() {
    asm volatile("cp.async.commit_group;" ::);
}
template <int NN>
__device__ __forceinline__ void cp_wait() {
    asm volatile("cp.async.wait_group %0;" :: "n"(NN));
}
__device__ __forceinline__ void mma_tf32(float* d, const unsigned* a, const unsigned* b) {
    asm volatile(
        "mma.sync.aligned.m16n8k8.row.col.f32.tf32.tf32.f32 "
        "{%0,%1,%2,%3}, {%4,%5,%6,%7}, {%8,%9}, {%0,%1,%2,%3};\n"
        : "+f"(d[0]), "+f"(d[1]), "+f"(d[2]), "+f"(d[3])
        : "r"(a[0]), "r"(a[1]), "r"(a[2]), "r"(a[3]), "r"(b[0]), "r"(b[1]));
}

template <bool ROUND, bool DUAL, bool IDX, bool DYN>
__global__ void __launch_bounds__(256, 1)
gemm_tf32(const float* __restrict__ A, const float* __restrict__ BT,
          const float* __restrict__ bias, float* __restrict__ C,
          float* __restrict__ C2, const int* __restrict__ idx,
          const int* __restrict__ cap, int N, int K) {
    extern __shared__ float smem[];
    const int tid = threadIdx.x, lane = tid & 31, warp = tid >> 5;
    const int wm = warp & 3, wn = warp >> 2;          // 4 warps M x 2 warps N
    const int m0 = blockIdx.y * 256, n0 = blockIdx.x * 128;
    if (DYN) { if (m0 >= __ldg(cap)) return; }

    const uint32_t sb = (uint32_t)__cvta_generic_to_shared(smem);

    // hoisted producer pointers (k-invariant)
    const float* aptr[8]; uint32_t adst[8];
#pragma unroll
    for (int i = 0; i < 8; i++) {
        const int c = tid + i * 256;                   // 2048 A chunks of 16B
        const int r = c >> 3, kc = c & 7;
        const int arow = IDX ? __ldg(idx + m0 + r) : (m0 + r);
        aptr[i] = A + (size_t)arow * K + kc * 4;
        adst[i] = (uint32_t)((r * SAF + kc * 4) * 4);
    }
    const float* bptr[4]; uint32_t bdst[4];
#pragma unroll
    for (int i = 0; i < 4; i++) {
        const int c = tid + i * 256;                   // 1024 B chunks
        const int r = c >> 3, kc = c & 7;
        bptr[i] = BT + (size_t)(n0 + r) * K + kc * 4;
        bdst[i] = (uint32_t)((A_FLOATS + r * SAF + kc * 4) * 4);
    }

    float acc[4][8][4];
#pragma unroll
    for (int i = 0; i < 4; i++)
#pragma unroll
        for (int j = 0; j < 8; j++)
#pragma unroll
            for (int q = 0; q < 4; q++) acc[i][j][q] = 0.f;

    auto load_tiles = [&](int kt, int b) {
        const int k0 = kt * 32;
        const uint32_t bb = sb + b * STG_BYTES;
#pragma unroll
        for (int i = 0; i < 8; i++) cp16s(bb + adst[i], aptr[i] + k0);
#pragma unroll
        for (int i = 0; i < 4; i++) cp16s(bb + bdst[i], bptr[i] + k0);
        cp_commit();
    };

    load_tiles(0, 0);
    const int nk = K / 32;
    int buf = 0;
    for (int kt = 0; kt < nk; ++kt) {
        if (kt + 1 < nk) { load_tiles(kt + 1, buf ^ 1); cp_wait<1>(); }
        else             { cp_wait<0>(); }
        __syncthreads();

        const float* as = smem + buf * STG_FLOATS;
        const float* bs = as + A_FLOATS;
#pragma unroll
        for (int ks = 0; ks < 4; ++ks) {
            const int kA = ks * 8 + (lane & 3);
            unsigned af[4][4];
#pragma unroll
            for (int mt = 0; mt < 4; ++mt) {
                const int r = wm * 64 + mt * 16 + (lane >> 2);
                af[mt][0] = __float_as_uint(as[r * SAF + kA]);
                af[mt][1] = __float_as_uint(as[(r + 8) * SAF + kA]);
                af[mt][2] = __float_as_uint(as[r * SAF + kA + 4]);
                af[mt][3] = __float_as_uint(as[(r + 8) * SAF + kA + 4]);
            }
#pragma unroll
            for (int nh = 0; nh < 2; ++nh) {
                unsigned bf[4][2];
#pragma unroll
                for (int nt = 0; nt < 4; ++nt) {
                    const int n_ = wn * 64 + (nh * 4 + nt) * 8 + (lane >> 2);
                    bf[nt][0] = __float_as_uint(bs[n_ * SAF + kA]);
                    bf[nt][1] = __float_as_uint(bs[n_ * SAF + kA + 4]);
                }
#pragma unroll
                for (int mt = 0; mt < 4; ++mt)
#pragma unroll
                    for (int nt = 0; nt < 4; ++nt)
                        mma_tf32(acc[mt][nh * 4 + nt], af[mt], bf[nt]);
            }
        }
        __syncthreads();
        buf ^= 1;
    }

    // epilogue
#pragma unroll
    for (int nt = 0; nt < 8; ++nt) {
        const int col = n0 + wn * 64 + nt * 8 + 2 * (lane & 3);
        const float b0v = bias[col], b1v = bias[col + 1];
#pragma unroll
        for (int mt = 0; mt < 4; ++mt) {
            const int row = m0 + wm * 64 + mt * 16 + (lane >> 2);
            float v0 = fmaxf(acc[mt][nt][0] + b0v, 0.f);
            float v1 = fmaxf(acc[mt][nt][1] + b1v, 0.f);
            float v2 = fmaxf(acc[mt][nt][2] + b0v, 0.f);
            float v3 = fmaxf(acc[mt][nt][3] + b1v, 0.f);
            const size_t o0 = (size_t)row * N + col;
            const size_t o1 = (size_t)(row + 8) * N + col;
            if (DUAL) {
                *(float2*)(C2 + o0) = make_float2(v0, v1);
                *(float2*)(C2 + o1) = make_float2(v2, v3);
            }
            if (ROUND) {
                v0 = rna_tf32(v0); v1 = rna_tf32(v1);
                v2 = rna_tf32(v2); v3 = rna_tf32(v3);
            }
            *(float2*)(C + o0) = make_float2(v0, v1);
            *(float2*)(C + o1) = make_float2(v2, v3);
        }
    }
}

// ---------------------------------------------------------------------------
// Head: per compact slot s (< cnt): y[idx[s]] = dot(G1[s,:512], Wo) + bo,
// t_out[idx[s]] = 1 (softmax over size-1 axis).
// ---------------------------------------------------------------------------
__global__ void head_kernel(const int* __restrict__ idx,
                            const int* __restrict__ cnt_ptr,
                            const float* __restrict__ G1,
                            const float* __restrict__ Wo,
                            const float* __restrict__ bo,
                            float* __restrict__ y, float* __restrict__ tout) {
    const int cnt = __ldg(cnt_ptr);
    const int slot = blockIdx.x * 8 + (threadIdx.x >> 5);
    if (slot >= cnt) return;
    const int lane = threadIdx.x & 31;
    const float* g = G1 + (size_t)slot * 512;
    float s = 0.f;
#pragma unroll
    for (int j = 0; j < 4; j++) {
        float4 gv = *(const float4*)(g + j * 128 + lane * 4);
        float4 wv = *(const float4*)(Wo + j * 128 + lane * 4);
        s += gv.x * wv.x + gv.y * wv.y + gv.z * wv.z + gv.w * wv.w;
    }
#pragma unroll
    for (int o = 16; o > 0; o >>= 1) s += __shfl_xor_sync(0xffffffffu, s, o);
    if (lane == 0) {
        const int orig = idx[slot];
        y[orig]    = s + bo[0];
        tout[orig] = 1.0f;
    }
}

// ---------------------------------------------------------------------------
extern "C" void kernel_launch(void* const* d_in, const int* in_sizes, int n_in,
                              void* d_out, int out_size) {
    const float* x   = (const float*)d_in[0];
    const int*   tr  = (const int*)  d_in[1];
    const float* Wx0 = (const float*)d_in[2];
    const float* bx0 = (const float*)d_in[3];
    const float* Wx1 = (const float*)d_in[4];
    const float* bx1 = (const float*)d_in[5];
    const float* Wx2 = (const float*)d_in[6];
    const float* bx2 = (const float*)d_in[7];
    const float* Wy0 = (const float*)d_in[8];
    const float* by0 = (const float*)d_in[9];
    const float* Wy1 = (const float*)d_in[10];
    const float* by1 = (const float*)d_in[11];
    const float* Wo  = (const float*)d_in[12];
    const float* bo  = (const float*)d_in[13];
    // Wt/bt dead: softmax over size-1 axis == 1.

    float* out  = (float*)d_out;
    float* y    = out;
    float* xemb = out + NROWS;
    float* tout = out + NROWS + (size_t)NROWS * 512;

    float* scr = nullptr;
    cudaGetSymbolAddress((void**)&scr, g_scratch);
    int* idx0 = nullptr; cudaGetSymbolAddress((void**)&idx0, g_idx0);
    int* idx1 = nullptr; cudaGetSymbolAddress((void**)&idx1, g_idx1);
    int* meta = nullptr; cudaGetSymbolAddress((void**)&meta, g_meta);

    float* Xr   = scr + OFF_XR;
    float* WX0T = scr + OFF_WX0;
    float* WX1T = scr + OFF_WX1;
    float* WX2T = scr + OFF_WX2;
    float* WY0T = scr + OFF_WY0;
    float* WY1T = scr + OFF_WY1;
    float* H0   = scr + OFF_H0;
    float* H1   = scr + OFF_H1;
    float* XEr  = scr + OFF_XER;
    float* G0a  = scr + OFF_G0A;
    float* G0b  = scr + OFF_G0B;
    float* G1a  = scr + OFF_G1A;
    float* G1b  = scr + OFF_G1B;

    cudaFuncSetAttribute(gemm_tf32<true,  false, false, false>,
                         cudaFuncAttributeMaxDynamicSharedMemorySize, GEMM_SMEM);
    cudaFuncSetAttribute(gemm_tf32<true,  true,  false, false>,
                         cudaFuncAttributeMaxDynamicSharedMemorySize, GEMM_SMEM);
    cudaFuncSetAttribute(gemm_tf32<true,  false, true,  true>,
                         cudaFuncAttributeMaxDynamicSharedMemorySize, GEMM_SMEM);
    cudaFuncSetAttribute(gemm_tf32<false, false, false, true>,
                         cudaFuncAttributeMaxDynamicSharedMemorySize, GEMM_SMEM);

    // ---- prep ----
    {
        int n4 = (int)((size_t)NROWS * 512 / 4);
        round4_kernel<<<(n4 + 255) / 256, 256>>>((const float4*)x, (float4*)Xr, n4);
    }
    dim3 tb(32, 8);
    transpose_round<<<dim3(2048 / 32, 512 / 32),  tb>>>(Wx0, WX0T, 512, 2048);
    transpose_round<<<dim3(2048 / 32, 2048 / 32), tb>>>(Wx1, WX1T, 2048, 2048);
    transpose_round<<<dim3(512 / 32, 2048 / 32),  tb>>>(Wx2, WX2T, 2048, 512);
    transpose_round<<<dim3(1024 / 32, 512 / 32),  tb>>>(Wy0, WY0T, 512, 1024);
    transpose_round<<<dim3(1024 / 32, 512 / 32),  tb>>>(Wy0 + (size_t)512 * 1024,
                                                        WY0T + (size_t)1024 * 512, 512, 1024);
    transpose_round<<<dim3(512 / 32, 1024 / 32),  tb>>>(Wy1, WY1T, 1024, 512);
    transpose_round<<<dim3(512 / 32, 1024 / 32),  tb>>>(Wy1 + (size_t)1024 * 512,
                                                        WY1T + (size_t)512 * 1024, 1024, 512);

    // ---- partition by treatment ----
    zero_meta_kernel<<<1, 32>>>();
    count_kernel<<<NROWS / 256, 256>>>(tr);
    scatter_kernel<<<NROWS / 256, 256>>>(tr);
    pad_kernel<<<1, 256>>>();

    const dim3 blk(256);
    const int MT = NROWS / 256;  // 256 M-tiles (dense / worst case)

    // trunk (dense)
    gemm_tf32<true, false, false, false><<<dim3(2048 / 128, MT), blk, GEMM_SMEM>>>(
        Xr, WX0T, bx0, H0, nullptr, nullptr, nullptr, 2048, 512);
    gemm_tf32<true, false, false, false><<<dim3(2048 / 128, MT), blk, GEMM_SMEM>>>(
        H0, WX1T, bx1, H1, nullptr, nullptr, nullptr, 2048, 2048);
    gemm_tf32<true, true, false, false><<<dim3(512 / 128, MT), blk, GEMM_SMEM>>>(
        H1, WX2T, bx2, XEr, xemb, nullptr, nullptr, 512, 2048);

    // experts (gathered, compact, early-exit past padded count)
    gemm_tf32<true, false, true, true><<<dim3(1024 / 128, MT), blk, GEMM_SMEM>>>(
        XEr, WY0T, by0, G0a, nullptr, idx0, meta + 1, 1024, 512);
    gemm_tf32<true, false, true, true><<<dim3(1024 / 128, MT), blk, GEMM_SMEM>>>(
        XEr, WY0T + (size_t)1024 * 512, by0 + 1024, G0b, nullptr, idx1, meta + 3, 1024, 512);
    gemm_tf32<false, false, false, true><<<dim3(512 / 128, MT), blk, GEMM_SMEM>>>(
        G0a, WY1T, by1, G1a, nullptr, nullptr, meta + 1, 512, 1024);
    gemm_tf32<false, false, false, true><<<dim3(512 / 128, MT), blk, GEMM_SMEM>>>(
        G0b, WY1T + (size_t)512 * 1024, by1 + 512, G1b, nullptr, nullptr, meta + 3, 512, 1024);

    // gathered heads (scatter y / t_out by original row)
    head_kernel<<<NROWS / 8, 256>>>(idx0, meta + 0, G1a, Wo,       bo,     y, tout);
    head_kernel<<<NROWS / 8, 256>>>(idx1, meta + 2, G1b, Wo + 512, bo + 1, y, tout);
}

// round 4
// speedup vs baseline: 1.1058x; 1.0094x over previous
#include <cuda_runtime.h>
#include <cstdint>
#include <cstddef>

// ---------------------------------------------------------------------------
// DeepCausalModel, legacy-tensor-core path (tcgen05 rejected by compute_103
// PTX target). TF32 mma.sync m16n8k8, CTA 256x128, warp 64x64, 4-stage
// cp.async pipeline with ONE barrier per ktile. Experts gathered by treatment.
// ---------------------------------------------------------------------------

#define NROWS 65536

// ---- fp32 scratch ----
constexpr size_t OFF_XR  = 0;                               // [N,512] rounded X
constexpr size_t OFF_WX0 = OFF_XR  + (size_t)NROWS * 512;   // [2048,512] (T)
constexpr size_t OFF_WX1 = OFF_WX0 + (size_t)512 * 2048;    // [2048,2048]
constexpr size_t OFF_WX2 = OFF_WX1 + (size_t)2048 * 2048;   // [512,2048]
constexpr size_t OFF_WY0 = OFF_WX2 + (size_t)2048 * 512;    // 2x [1024,512]
constexpr size_t OFF_WY1 = OFF_WY0 + (size_t)2 * 512 * 1024;// 2x [512,1024]
constexpr size_t OFF_H0  = OFF_WY1 + (size_t)2 * 1024 * 512;// [N,2048]
constexpr size_t OFF_H1  = OFF_H0  + (size_t)NROWS * 2048;  // [N,2048]
constexpr size_t OFF_XER = OFF_H1  + (size_t)NROWS * 2048;  // [N,512]
constexpr size_t SCR_TOTAL = OFF_XER + (size_t)NROWS * 512;
constexpr size_t OFF_G0A = OFF_H0;
constexpr size_t OFF_G0B = OFF_H0 + (size_t)NROWS * 1024;
constexpr size_t OFF_G1A = OFF_H1;
constexpr size_t OFF_G1B = OFF_H1 + (size_t)NROWS * 512;

__device__ float g_scratch[SCR_TOTAL];
__device__ int   g_idx0[NROWS];
__device__ int   g_idx1[NROWS];
__device__ int   g_meta[8];  // [0]=cnt0 [1]=pad0 [2]=cnt1 [3]=pad1 [4],[5]=cursors

// ---------------------------------------------------------------------------
__device__ __forceinline__ float rna_tf32(float x) {
    unsigned u;
    asm("cvt.rna.tf32.f32 %0, %1;" : "=r"(u) : "f"(x));
    return __uint_as_float(u);
}

__global__ void round4_kernel(const float4* __restrict__ in,
                              float4* __restrict__ out, int n4) {
    int i = blockIdx.x * blockDim.x + threadIdx.x;
    if (i < n4) {
        float4 v = in[i];
        v.x = rna_tf32(v.x); v.y = rna_tf32(v.y);
        v.z = rna_tf32(v.z); v.w = rna_tf32(v.w);
        out[i] = v;
    }
}

// ---------------------------------------------------------------------------
// fused weight transpose+round: all 7 [K,N]->[N,K] transposes in one launch
// ---------------------------------------------------------------------------
__device__ __forceinline__ void do_transpose32(const float* W, float* WT,
                                               int K, int N, int bx, int by) {
    __shared__ float t[32][33];
    const int x = threadIdx.x, y = threadIdx.y;
#pragma unroll
    for (int i = 0; i < 32; i += 8)
        t[y + i][x] = W[(size_t)(by + y + i) * N + bx + x];
    __syncthreads();
#pragma unroll
    for (int i = 0; i < 32; i += 8)
        WT[(size_t)(bx + y + i) * K + by + x] = rna_tf32(t[x][y + i]);
}

// segment block counts
constexpr int TS0 = (512 / 32)  * (2048 / 32);  // Wx0: 1024
constexpr int TS1 = (2048 / 32) * (2048 / 32);  // Wx1: 4096
constexpr int TS2 = (2048 / 32) * (512 / 32);   // Wx2: 1024
constexpr int TS3 = (512 / 32)  * (1024 / 32);  // Wy0[0]: 512
constexpr int TS4 = TS3;                        // Wy0[1]
constexpr int TS5 = (1024 / 32) * (512 / 32);   // Wy1[0]: 512
constexpr int TS6 = TS5;                        // Wy1[1]
constexpr int TS_TOTAL = TS0 + TS1 + TS2 + TS3 + TS4 + TS5 + TS6;  // 8192

__global__ void prep_transpose(const float* __restrict__ Wx0,
                               const float* __restrict__ Wx1,
                               const float* __restrict__ Wx2,
                               const float* __restrict__ Wy0,
                               const float* __restrict__ Wy1,
                               float* __restrict__ scr) {
    int b = blockIdx.x;
    const float* W; float* WT; int K, N, tx;
    if (b < TS0) {
        W = Wx0; WT = scr + OFF_WX0; K = 512;  N = 2048; tx = 64;
    } else if ((b -= TS0) < TS1) {
        W = Wx1; WT = scr + OFF_WX1; K = 2048; N = 2048; tx = 64;
    } else if ((b -= TS1) < TS2) {
        W = Wx2; WT = scr + OFF_WX2; K = 2048; N = 512;  tx = 16;
    } else if ((b -= TS2) < TS3) {
        W = Wy0; WT = scr + OFF_WY0; K = 512;  N = 1024; tx = 32;
    } else if ((b -= TS3) < TS4) {
        W = Wy0 + (size_t)512 * 1024; WT = scr + OFF_WY0 + (size_t)1024 * 512;
        K = 512;  N = 1024; tx = 32;
    } else if ((b -= TS4) < TS5) {
        W = Wy1; WT = scr + OFF_WY1; K = 1024; N = 512;  tx = 16;
    } else {
        b -= TS5;
        W = Wy1 + (size_t)1024 * 512; WT = scr + OFF_WY1 + (size_t)512 * 1024;
        K = 1024; N = 512;  tx = 16;
    }
    do_transpose32(W, WT, K, N, (b % tx) * 32, (b / tx) * 32);
}

// ---------------------------------------------------------------------------
// partition rows by treatment (int64-or-int32 buffer autodetect)
// ---------------------------------------------------------------------------
__device__ __forceinline__ int detect64(const int* tr) {
    int a = 0;
#pragma unroll
    for (int i = 1; i < 64; i += 2) a |= tr[i];
    return (a == 0) ? 1 : 0;
}

__global__ void zero_meta_kernel() {
    if (threadIdx.x < 8) g_meta[threadIdx.x] = 0;
}

__global__ void scatter_kernel(const int* __restrict__ tr) {
    __shared__ int s64;
    if (threadIdx.x == 0) s64 = detect64(tr);
    __syncthreads();
    const int row = blockIdx.x * 256 + threadIdx.x;
    const int t = s64 ? tr[2 * row] : tr[row];
    const unsigned full = 0xffffffffu;
    const unsigned mask0 = __ballot_sync(full, t == 0);
    const int c0 = __popc(mask0);
    int b0 = 0, b1 = 0;
    if ((threadIdx.x & 31) == 0) {
        b0 = atomicAdd(&g_meta[4], c0);
        b1 = atomicAdd(&g_meta[5], 32 - c0);
    }
    b0 = __shfl_sync(full, b0, 0);
    b1 = __shfl_sync(full, b1, 0);
    const unsigned lt = (1u << (threadIdx.x & 31)) - 1u;
    if (t == 0) g_idx0[b0 + __popc(mask0 & lt)] = row;
    else        g_idx1[b1 + __popc((~mask0) & lt)] = row;
}

__global__ void pad_kernel() {
    const int cnt0 = g_meta[4];   // scatter cursors hold the final counts
    const int cnt1 = g_meta[5];
    const int p0 = (cnt0 + 255) & ~255;
    const int p1 = (cnt1 + 255) & ~255;
    if (threadIdx.x == 0) {
        g_meta[0] = cnt0; g_meta[1] = p0;
        g_meta[2] = cnt1; g_meta[3] = p1;
    }
    const int f0 = (cnt0 > 0) ? g_idx0[0] : 0;
    const int f1 = (cnt1 > 0) ? g_idx1[0] : 0;
    for (int i = cnt0 + threadIdx.x; i < p0; i += 256) g_idx0[i] = f0;
    for (int i = cnt1 + threadIdx.x; i < p1; i += 256) g_idx1[i] = f1;
}

// ---------------------------------------------------------------------------
// TF32 GEMM: C[M,N] = relu(A[M,K] @ BT[N,K]^T + bias)
// CTA 256x128, warp 64x64, BK=32, 4-stage cp.async, 1 barrier/ktile.
// ---------------------------------------------------------------------------
constexpr int SAF = 36;                           // smem row stride (floats)
constexpr int A_FLOATS = 256 * SAF;               // 9216
constexpr int STG_FLOATS = A_FLOATS + 128 * SAF;  // 13824
constexpr int STG_BYTES = STG_FLOATS * 4;         // 55296
constexpr int NSTAGE = 4;
constexpr int GEMM_SMEM = NSTAGE * STG_BYTES;     // 221184

__device__ __forceinline__ void cp16s(uint32_t daddr, const float* src) {
    asm volatile("cp.async.cg.shared.global [%0], [%1], 16;" :: "r"(daddr), "l"(src));
}
__device__ __forceinline__ void cp_commit() {
    asm volatile("cp.async.commit_group;" ::);
}
template <int NN>
__device__ __forceinline__ void cp_wait() {
    asm volatile("cp.async.wait_group %0;" :: "n"(NN));
}
__device__ __forceinline__ void mma_tf32(float* d, const unsigned* a, const unsigned* b) {
    asm volatile(
        "mma.sync.aligned.m16n8k8.row.col.f32.tf32.tf32.f32 "
        "{%0,%1,%2,%3}, {%4,%5,%6,%7}, {%8,%9}, {%0,%1,%2,%3};\n"
        : "+f"(d[0]), "+f"(d[1]), "+f"(d[2]), "+f"(d[3])
        : "r"(a[0]), "r"(a[1]), "r"(a[2]), "r"(a[3]), "r"(b[0]), "r"(b[1]));
}

template <bool ROUND, bool DUAL, bool IDX, bool DYN>
__global__ void __launch_bounds__(256, 1)
gemm_tf32(const float* __restrict__ A, const float* __restrict__ BT,
          const float* __restrict__ bias, float* __restrict__ C,
          float* __restrict__ C2, const int* __restrict__ idx,
          const int* __restrict__ cap, int N, int K) {
    extern __shared__ float smem[];
    const int tid = threadIdx.x, lane = tid & 31, warp = tid >> 5;
    const int wm = warp & 3, wn = warp >> 2;      // 4 warps M x 2 warps N
    const int m0 = blockIdx.y * 256, n0 = blockIdx.x * 128;
    if (DYN) { if (m0 >= __ldg(cap)) return; }

    const uint32_t sb = (uint32_t)__cvta_generic_to_shared(smem);

    // hoisted producer pointers (k-invariant)
    const float* aptr[8]; uint32_t adst[8];
#pragma unroll
    for (int i = 0; i < 8; i++) {
        const int c = tid + i * 256;               // 2048 A chunks of 16B
        const int r = c >> 3, kc = c & 7;
        const int arow = IDX ? __ldg(idx + m0 + r) : (m0 + r);
        aptr[i] = A + (size_t)arow * K + kc * 4;
        adst[i] = (uint32_t)((r * SAF + kc * 4) * 4);
    }
    const float* bptr[4]; uint32_t bdst[4];
#pragma unroll
    for (int i = 0; i < 4; i++) {
        const int c = tid + i * 256;               // 1024 B chunks
        const int r = c >> 3, kc = c & 7;
        bptr[i] = BT + (size_t)(n0 + r) * K + kc * 4;
        bdst[i] = (uint32_t)((A_FLOATS + r * SAF + kc * 4) * 4);
    }

    float acc[4][8][4];
#pragma unroll
    for (int i = 0; i < 4; i++)
#pragma unroll
        for (int j = 0; j < 8; j++)
#pragma unroll
            for (int q = 0; q < 4; q++) acc[i][j][q] = 0.f;

    auto load_tiles = [&](int kt) {
        const int k0 = kt * 32;
        const uint32_t bb = sb + (uint32_t)(kt & (NSTAGE - 1)) * STG_BYTES;
#pragma unroll
        for (int i = 0; i < 8; i++) cp16s(bb + adst[i], aptr[i] + k0);
#pragma unroll
        for (int i = 0; i < 4; i++) cp16s(bb + bdst[i], bptr[i] + k0);
        cp_commit();
    };

    const int nk = K / 32;
    load_tiles(0); load_tiles(1); load_tiles(2);   // 3 groups in flight

    for (int kt = 0; kt < nk; ++kt) {
        cp_wait<2>();        // group kt complete (issued = kt+3 before this iter)
        __syncthreads();     // data visible to all; all warps done with kt-1
        if (kt + 3 < nk) load_tiles(kt + 3);       // overwrites stage (kt-1)&3
        else cp_commit();                          // keep group count exact

        const float* as = smem + (size_t)(kt & (NSTAGE - 1)) * STG_FLOATS;
        const float* bs = as + A_FLOATS;
#pragma unroll
        for (int ks = 0; ks < 4; ++ks) {
            const int kA = ks * 8 + (lane & 3);
            unsigned af[4][4];
#pragma unroll
            for (int mt = 0; mt < 4; ++mt) {
                const int r = wm * 64 + mt * 16 + (lane >> 2);
                af[mt][0] = __float_as_uint(as[r * SAF + kA]);
                af[mt][1] = __float_as_uint(as[(r + 8) * SAF + kA]);
                af[mt][2] = __float_as_uint(as[r * SAF + kA + 4]);
                af[mt][3] = __float_as_uint(as[(r + 8) * SAF + kA + 4]);
            }
#pragma unroll
            for (int nh = 0; nh < 2; ++nh) {
                unsigned bf[4][2];
#pragma unroll
                for (int nt = 0; nt < 4; ++nt) {
                    const int n_ = wn * 64 + (nh * 4 + nt) * 8 + (lane >> 2);
                    bf[nt][0] = __float_as_uint(bs[n_ * SAF + kA]);
                    bf[nt][1] = __float_as_uint(bs[n_ * SAF + kA + 4]);
                }
#pragma unroll
                for (int mt = 0; mt < 4; ++mt)
#pragma unroll
                    for (int nt = 0; nt < 4; ++nt)
                        mma_tf32(acc[mt][nh * 4 + nt], af[mt], bf[nt]);
            }
        }
    }

    // epilogue
#pragma unroll
    for (int nt = 0; nt < 8; ++nt) {
        const int col = n0 + wn * 64 + nt * 8 + 2 * (lane & 3);
        const float b0v = bias[col], b1v = bias[col + 1];
#pragma unroll
        for (int mt = 0; mt < 4; ++mt) {
            const int row = m0 + wm * 64 + mt * 16 + (lane >> 2);
            float v0 = fmaxf(acc[mt][nt][0] + b0v, 0.f);
            float v1 = fmaxf(acc[mt][nt][1] + b1v, 0.f);
            float v2 = fmaxf(acc[mt][nt][2] + b0v, 0.f);
            float v3 = fmaxf(acc[mt][nt][3] + b1v, 0.f);
            const size_t o0 = (size_t)row * N + col;
            const size_t o1 = (size_t)(row + 8) * N + col;
            if (DUAL) {
                *(float2*)(C2 + o0) = make_float2(v0, v1);
                *(float2*)(C2 + o1) = make_float2(v2, v3);
            }
            if (ROUND) {
                v0 = rna_tf32(v0); v1 = rna_tf32(v1);
                v2 = rna_tf32(v2); v3 = rna_tf32(v3);
            }
            *(float2*)(C + o0) = make_float2(v0, v1);
            *(float2*)(C + o1) = make_float2(v2, v3);
        }
    }
}

// ---------------------------------------------------------------------------
// Head: per compact slot s (< cnt): y[idx[s]] = dot(G1[s,:512], Wo) + bo,
// t_out[idx[s]] = 1 (softmax over size-1 axis).
// ---------------------------------------------------------------------------
__global__ void head_kernel(const int* __restrict__ idx,
                            const int* __restrict__ cnt_ptr,
                            const float* __restrict__ G1,
                            const float* __restrict__ Wo,
                            const float* __restrict__ bo,
                            float* __restrict__ y, float* __restrict__ tout) {
    const int cnt = __ldg(cnt_ptr);
    const int slot = blockIdx.x * 8 + (threadIdx.x >> 5);
    if (slot >= cnt) return;
    const int lane = threadIdx.x & 31;
    const float* g = G1 + (size_t)slot * 512;
    float s = 0.f;
#pragma unroll
    for (int j = 0; j < 4; j++) {
        float4 gv = *(const float4*)(g + j * 128 + lane * 4);
        float4 wv = *(const float4*)(Wo + j * 128 + lane * 4);
        s += gv.x * wv.x + gv.y * wv.y + gv.z * wv.z + gv.w * wv.w;
    }
#pragma unroll
    for (int o = 16; o > 0; o >>= 1) s += __shfl_xor_sync(0xffffffffu, s, o);
    if (lane == 0) {
        const int orig = idx[slot];
        y[orig]    = s + bo[0];
        tout[orig] = 1.0f;
    }
}

// ---------------------------------------------------------------------------
extern "C" void kernel_launch(void* const* d_in, const int* in_sizes, int n_in,
                              void* d_out, int out_size) {
    const float* x   = (const float*)d_in[0];
    const int*   tr  = (const int*)  d_in[1];
    const float* Wx0 = (const float*)d_in[2];
    const float* bx0 = (const float*)d_in[3];
    const float* Wx1 = (const float*)d_in[4];
    const float* bx1 = (const float*)d_in[5];
    const float* Wx2 = (const float*)d_in[6];
    const float* bx2 = (const float*)d_in[7];
    const float* Wy0 = (const float*)d_in[8];
    const float* by0 = (const float*)d_in[9];
    const float* Wy1 = (const float*)d_in[10];
    const float* by1 = (const float*)d_in[11];
    const float* Wo  = (const float*)d_in[12];
    const float* bo  = (const float*)d_in[13];
    // Wt/bt dead: softmax over size-1 axis == 1.

    float* out  = (float*)d_out;
    float* y    = out;
    float* xemb = out + NROWS;
    float* tout = out + NROWS + (size_t)NROWS * 512;

    float* scr = nullptr;
    cudaGetSymbolAddress((void**)&scr, g_scratch);
    int* idx0 = nullptr; cudaGetSymbolAddress((void**)&idx0, g_idx0);
    int* idx1 = nullptr; cudaGetSymbolAddress((void**)&idx1, g_idx1);
    int* meta = nullptr; cudaGetSymbolAddress((void**)&meta, g_meta);

    float* Xr   = scr + OFF_XR;
    float* WX0T = scr + OFF_WX0;
    float* WX1T = scr + OFF_WX1;
    float* WX2T = scr + OFF_WX2;
    float* WY0T = scr + OFF_WY0;
    float* WY1T = scr + OFF_WY1;
    float* H0   = scr + OFF_H0;
    float* H1   = scr + OFF_H1;
    float* XEr  = scr + OFF_XER;
    float* G0a  = scr + OFF_G0A;
    float* G0b  = scr + OFF_G0B;
    float* G1a  = scr + OFF_G1A;
    float* G1b  = scr + OFF_G1B;

    cudaFuncSetAttribute(gemm_tf32<true,  false, false, false>,
                         cudaFuncAttributeMaxDynamicSharedMemorySize, GEMM_SMEM);
    cudaFuncSetAttribute(gemm_tf32<true,  true,  false, false>,
                         cudaFuncAttributeMaxDynamicSharedMemorySize, GEMM_SMEM);
    cudaFuncSetAttribute(gemm_tf32<true,  false, true,  true>,
                         cudaFuncAttributeMaxDynamicSharedMemorySize, GEMM_SMEM);
    cudaFuncSetAttribute(gemm_tf32<false, false, false, true>,
                         cudaFuncAttributeMaxDynamicSharedMemorySize, GEMM_SMEM);

    // launches 0-4: partition + prep (ncu -s 5 -c 1 then lands on GEMM1)
    zero_meta_kernel<<<1, 32>>>();
    scatter_kernel<<<NROWS / 256, 256>>>(tr);
    pad_kernel<<<1, 256>>>();
    {
        int n4 = (int)((size_t)NROWS * 512 / 4);
        round4_kernel<<<(n4 + 255) / 256, 256>>>((const float4*)x, (float4*)Xr, n4);
    }
    prep_transpose<<<TS_TOTAL, dim3(32, 8)>>>(Wx0, Wx1, Wx2, Wy0, Wy1, scr);

    const dim3 blk(256);
    const int MT = NROWS / 256;  // 256 M-tiles (dense / worst case)

    // trunk (dense)
    gemm_tf32<true, false, false, false><<<dim3(2048 / 128, MT), blk, GEMM_SMEM>>>(
        Xr, WX0T, bx0, H0, nullptr, nullptr, nullptr, 2048, 512);
    gemm_tf32<true, false, false, false><<<dim3(2048 / 128, MT), blk, GEMM_SMEM>>>(
        H0, WX1T, bx1, H1, nullptr, nullptr, nullptr, 2048, 2048);
    gemm_tf32<true, true, false, false><<<dim3(512 / 128, MT), blk, GEMM_SMEM>>>(
        H1, WX2T, bx2, XEr, xemb, nullptr, nullptr, 512, 2048);

    // experts (gathered, compact, early-exit past padded count)
    gemm_tf32<true, false, true, true><<<dim3(1024 / 128, MT), blk, GEMM_SMEM>>>(
        XEr, WY0T, by0, G0a, nullptr, idx0, meta + 1, 1024, 512);
    gemm_tf32<true, false, true, true><<<dim3(1024 / 128, MT), blk, GEMM_SMEM>>>(
        XEr, WY0T + (size_t)1024 * 512, by0 + 1024, G0b, nullptr, idx1, meta + 3, 1024, 512);
    gemm_tf32<false, false, false, true><<<dim3(512 / 128, MT), blk, GEMM_SMEM>>>(
        G0a, WY1T, by1, G1a, nullptr, nullptr, meta + 1, 512, 1024);
    gemm_tf32<false, false, false, true><<<dim3(512 / 128, MT), blk, GEMM_SMEM>>>(
        G0b, WY1T + (size_t)512 * 1024, by1 + 512, G1b, nullptr, nullptr, meta + 3, 512, 1024);

    // gathered heads (scatter y / t_out by original row)
    head_kernel<<<NROWS / 8, 256>>>(idx0, meta + 0, G1a, Wo,       bo,     y, tout);
    head_kernel<<<NROWS / 8, 256>>>(idx1, meta + 2, G1b, Wo + 512, bo + 1, y, tout);
}

// round 5
// speedup vs baseline: 2.2000x; 1.9895x over previous
#include <cuda_runtime.h>
#include <cuda_fp16.h>
#include <cstdint>
#include <cstddef>

// ---------------------------------------------------------------------------
// DeepCausalModel. Legacy tensor path (tcgen05 blocked by compute_103 PTX).
// R1-R4 evidence: tf32 HMMA issue-rate bound at ~341 MACs/cyc/SM. Switch to
// fp16 mma.m16n8k16 (2x MACs/instr, same 11-bit significand as tf32).
// CTA 256x128, warp 64x64, BK=64 halves, SW128 swizzle + ldmatrix.x4,
// 4-stage cp.async, 1 barrier/ktile. Experts gathered by treatment.
// ---------------------------------------------------------------------------

#define NROWS 65536

// ---- fp16 scratch (element offsets, halves) ----
constexpr size_t OFF_XH  = 0;                                // [N,512]
constexpr size_t OFF_WX0 = OFF_XH  + (size_t)NROWS * 512;    // [2048,512] (T)
constexpr size_t OFF_WX1 = OFF_WX0 + (size_t)512 * 2048;     // [2048,2048]
constexpr size_t OFF_WX2 = OFF_WX1 + (size_t)2048 * 2048;    // [512,2048]
constexpr size_t OFF_WY0 = OFF_WX2 + (size_t)2048 * 512;     // 2x [1024,512]
constexpr size_t OFF_WY1 = OFF_WY0 + (size_t)2 * 512 * 1024; // 2x [512,1024]
constexpr size_t OFF_H0  = OFF_WY1 + (size_t)2 * 1024 * 512; // [N,2048]
constexpr size_t OFF_H1  = OFF_H0  + (size_t)NROWS * 2048;   // [N,2048]
constexpr size_t OFF_XEH = OFF_H1  + (size_t)NROWS * 2048;   // [N,512]
constexpr size_t SCR_TOTAL = OFF_XEH + (size_t)NROWS * 512;
constexpr size_t OFF_G0A = OFF_H0;
constexpr size_t OFF_G0B = OFF_H0 + (size_t)NROWS * 1024;
constexpr size_t OFF_G1A = OFF_H1;
constexpr size_t OFF_G1B = OFF_H1 + (size_t)NROWS * 512;

__device__ __half g_scratch[SCR_TOTAL];
__device__ int    g_idx0[NROWS];
__device__ int    g_idx1[NROWS];
__device__ int    g_meta[8];  // [0]=cnt0 [1]=pad0 [2]=cnt1 [3]=pad1 [4],[5]=cursors

// ---------------------------------------------------------------------------
// prep: fp32 -> fp16 conversions
// ---------------------------------------------------------------------------
__global__ void cvt_half_kernel(const float4* __restrict__ in,
                                __half* __restrict__ out, int n8) {
    int i = blockIdx.x * blockDim.x + threadIdx.x;
    if (i < n8) {
        float4 v0 = in[2 * i], v1 = in[2 * i + 1];
        __half2 h0 = __floats2half2_rn(v0.x, v0.y);
        __half2 h1 = __floats2half2_rn(v0.z, v0.w);
        __half2 h2 = __floats2half2_rn(v1.x, v1.y);
        __half2 h3 = __floats2half2_rn(v1.z, v1.w);
        uint4 o;
        o.x = *(unsigned*)&h0; o.y = *(unsigned*)&h1;
        o.z = *(unsigned*)&h2; o.w = *(unsigned*)&h3;
        *(uint4*)(out + (size_t)8 * i) = o;
    }
}

// fused weight transpose+convert: [K,N] fp32 -> [N,K] fp16, all 7 matrices
__device__ __forceinline__ void do_transpose32(const float* W, __half* WT,
                                               int K, int N, int bx, int by) {
    __shared__ float t[32][33];
    const int x = threadIdx.x, y = threadIdx.y;
#pragma unroll
    for (int i = 0; i < 32; i += 8)
        t[y + i][x] = W[(size_t)(by + y + i) * N + bx + x];
    __syncthreads();
#pragma unroll
    for (int i = 0; i < 32; i += 8)
        WT[(size_t)(bx + y + i) * K + by + x] = __float2half_rn(t[x][y + i]);
}

constexpr int TS0 = (512 / 32)  * (2048 / 32);
constexpr int TS1 = (2048 / 32) * (2048 / 32);
constexpr int TS2 = (2048 / 32) * (512 / 32);
constexpr int TS3 = (512 / 32)  * (1024 / 32);
constexpr int TS4 = TS3;
constexpr int TS5 = (1024 / 32) * (512 / 32);
constexpr int TS_TOTAL = TS0 + TS1 + TS2 + TS3 + TS4 + TS5 + TS5;

__global__ void prep_transpose(const float* __restrict__ Wx0,
                               const float* __restrict__ Wx1,
                               const float* __restrict__ Wx2,
                               const float* __restrict__ Wy0,
                               const float* __restrict__ Wy1,
                               __half* __restrict__ scr) {
    int b = blockIdx.x;
    const float* W; __half* WT; int K, N, tx;
    if (b < TS0) {
        W = Wx0; WT = scr + OFF_WX0; K = 512;  N = 2048; tx = 64;
    } else if ((b -= TS0) < TS1) {
        W = Wx1; WT = scr + OFF_WX1; K = 2048; N = 2048; tx = 64;
    } else if ((b -= TS1) < TS2) {
        W = Wx2; WT = scr + OFF_WX2; K = 2048; N = 512;  tx = 16;
    } else if ((b -= TS2) < TS3) {
        W = Wy0; WT = scr + OFF_WY0; K = 512;  N = 1024; tx = 32;
    } else if ((b -= TS3) < TS4) {
        W = Wy0 + (size_t)512 * 1024; WT = scr + OFF_WY0 + (size_t)1024 * 512;
        K = 512;  N = 1024; tx = 32;
    } else if ((b -= TS4) < TS5) {
        W = Wy1; WT = scr + OFF_WY1; K = 1024; N = 512;  tx = 16;
    } else {
        b -= TS5;
        W = Wy1 + (size_t)1024 * 512; WT = scr + OFF_WY1 + (size_t)512 * 1024;
        K = 1024; N = 512;  tx = 16;
    }
    do_transpose32(W, WT, K, N, (b % tx) * 32, (b / tx) * 32);
}

// ---------------------------------------------------------------------------
// partition rows by treatment (int64-or-int32 buffer autodetect)
// ---------------------------------------------------------------------------
__device__ __forceinline__ int detect64(const int* tr) {
    int a = 0;
#pragma unroll
    for (int i = 1; i < 64; i += 2) a |= tr[i];
    return (a == 0) ? 1 : 0;
}

__global__ void zero_meta_kernel() {
    if (threadIdx.x < 8) g_meta[threadIdx.x] = 0;
}

__global__ void scatter_kernel(const int* __restrict__ tr) {
    __shared__ int s64;
    if (threadIdx.x == 0) s64 = detect64(tr);
    __syncthreads();
    const int row = blockIdx.x * 256 + threadIdx.x;
    const int t = s64 ? tr[2 * row] : tr[row];
    const unsigned full = 0xffffffffu;
    const unsigned mask0 = __ballot_sync(full, t == 0);
    const int c0 = __popc(mask0);
    int b0 = 0, b1 = 0;
    if ((threadIdx.x & 31) == 0) {
        b0 = atomicAdd(&g_meta[4], c0);
        b1 = atomicAdd(&g_meta[5], 32 - c0);
    }
    b0 = __shfl_sync(full, b0, 0);
    b1 = __shfl_sync(full, b1, 0);
    const unsigned lt = (1u << (threadIdx.x & 31)) - 1u;
    if (t == 0) g_idx0[b0 + __popc(mask0 & lt)] = row;
    else        g_idx1[b1 + __popc((~mask0) & lt)] = row;
}

__global__ void pad_kernel() {
    const int cnt0 = g_meta[4];
    const int cnt1 = g_meta[5];
    const int p0 = (cnt0 + 255) & ~255;
    const int p1 = (cnt1 + 255) & ~255;
    if (threadIdx.x == 0) {
        g_meta[0] = cnt0; g_meta[1] = p0;
        g_meta[2] = cnt1; g_meta[3] = p1;
    }
    const int f0 = (cnt0 > 0) ? g_idx0[0] : 0;
    const int f1 = (cnt1 > 0) ? g_idx1[0] : 0;
    for (int i = cnt0 + threadIdx.x; i < p0; i += 256) g_idx0[i] = f0;
    for (int i = cnt1 + threadIdx.x; i < p1; i += 256) g_idx1[i] = f1;
}

// ---------------------------------------------------------------------------
// fp16 GEMM: C[M,N] = relu(A[M,K] @ BT[N,K]^T + bias), fp32 accumulate.
// A,BT,C fp16; bias fp32; optional fp32 dual store (x_emb).
// ---------------------------------------------------------------------------
constexpr int A_BYTES = 256 * 64 * 2;       // 32768
constexpr int B_BYTES = 128 * 64 * 2;       // 16384
constexpr int STG_BYTES = A_BYTES + B_BYTES;// 49152
constexpr int NSTAGE = 4;
constexpr int GEMM_SMEM = NSTAGE * STG_BYTES;  // 196608

__device__ __forceinline__ void cp16s(uint32_t daddr, const void* src) {
    asm volatile("cp.async.cg.shared.global [%0], [%1], 16;" :: "r"(daddr), "l"(src));
}
__device__ __forceinline__ void cp_commit() {
    asm volatile("cp.async.commit_group;" ::);
}
template <int NN>
__device__ __forceinline__ void cp_wait() {
    asm volatile("cp.async.wait_group %0;" :: "n"(NN));
}
__device__ __forceinline__ void ldmx4(unsigned* r, uint32_t addr) {
    asm volatile("ldmatrix.sync.aligned.m8n8.x4.shared.b16 {%0,%1,%2,%3}, [%4];"
                 : "=r"(r[0]), "=r"(r[1]), "=r"(r[2]), "=r"(r[3]) : "r"(addr));
}
__device__ __forceinline__ void mma16816(float* d, const unsigned* a,
                                         unsigned b0, unsigned b1) {
    asm volatile(
        "mma.sync.aligned.m16n8k16.row.col.f32.f16.f16.f32 "
        "{%0,%1,%2,%3}, {%4,%5,%6,%7}, {%8,%9}, {%0,%1,%2,%3};\n"
        : "+f"(d[0]), "+f"(d[1]), "+f"(d[2]), "+f"(d[3])
        : "r"(a[0]), "r"(a[1]), "r"(a[2]), "r"(a[3]), "r"(b0), "r"(b1));
}

template <bool DUAL, bool IDX, bool DYN>
__global__ void __launch_bounds__(256, 1)
gemm_fp16(const __half* __restrict__ A, const __half* __restrict__ BT,
          const float* __restrict__ bias, __half* __restrict__ C,
          float* __restrict__ C2, const int* __restrict__ idx,
          const int* __restrict__ cap, int N, int K) {
    extern __shared__ char smem[];
    const int tid = threadIdx.x, lane = tid & 31, warp = tid >> 5;
    const int wm = warp & 3, wn = warp >> 2;      // 4 warps M x 2 warps N
    const int m0 = blockIdx.y * 256, n0 = blockIdx.x * 128;
    if (DYN) { if (m0 >= __ldg(cap)) return; }

    const uint32_t sb = (uint32_t)__cvta_generic_to_shared(smem);

    // producer: k-invariant pointers. A: 2048 16B chunks, B: 1024.
    const __half* aptr[8]; uint32_t adst[8];
#pragma unroll
    for (int i = 0; i < 8; i++) {
        const int c = tid + i * 256;
        const int r = c >> 3, kc = c & 7;
        const int arow = IDX ? __ldg(idx + m0 + r) : (m0 + r);
        aptr[i] = A + (size_t)arow * K + kc * 8;
        adst[i] = (uint32_t)(r * 128 + ((kc ^ (r & 7)) << 4));
    }
    const __half* bptr[4]; uint32_t bdst[4];
#pragma unroll
    for (int i = 0; i < 4; i++) {
        const int c = tid + i * 256;
        const int r = c >> 3, kc = c & 7;
        bptr[i] = BT + (size_t)(n0 + r) * K + kc * 8;
        bdst[i] = (uint32_t)(A_BYTES + r * 128 + ((kc ^ (r & 7)) << 4));
    }

    float acc[4][8][4];
#pragma unroll
    for (int i = 0; i < 4; i++)
#pragma unroll
        for (int j = 0; j < 8; j++)
#pragma unroll
            for (int q = 0; q < 4; q++) acc[i][j][q] = 0.f;

    auto load_tiles = [&](int kt) {
        const int k0 = kt * 64;
        const uint32_t bb = sb + (uint32_t)(kt & (NSTAGE - 1)) * STG_BYTES;
#pragma unroll
        for (int i = 0; i < 8; i++) cp16s(bb + adst[i], aptr[i] + k0);
#pragma unroll
        for (int i = 0; i < 4; i++) cp16s(bb + bdst[i], bptr[i] + k0);
        cp_commit();
    };

    const int nk = K / 64;
    load_tiles(0); load_tiles(1); load_tiles(2);

    // consumer ldmatrix address components (swizzle xor folds to lrow)
    const int lrow = lane & 7;
    const int g8 = (lane >> 3) & 1;
    const int kg = lane >> 4;
    const uint32_t aoffs = (uint32_t)((wm * 64 + g8 * 8 + lrow) * 128);
    const uint32_t boffs = (uint32_t)(A_BYTES + (wn * 64 + g8 * 8 + lrow) * 128);

    for (int kt = 0; kt < nk; ++kt) {
        cp_wait<2>();
        __syncthreads();
        if (kt + 3 < nk) load_tiles(kt + 3);
        else cp_commit();

        const uint32_t st = sb + (uint32_t)(kt & (NSTAGE - 1)) * STG_BYTES;
#pragma unroll
        for (int ks = 0; ks < 4; ++ks) {
            const uint32_t kxo = (uint32_t)((((ks * 2 + kg) ^ lrow)) << 4);
            unsigned a[4][4];
#pragma unroll
            for (int mt = 0; mt < 4; ++mt)
                ldmx4(a[mt], st + aoffs + mt * 2048 + kxo);
            unsigned b[4][4];
#pragma unroll
            for (int np = 0; np < 4; ++np)
                ldmx4(b[np], st + boffs + np * 2048 + kxo);
#pragma unroll
            for (int mt = 0; mt < 4; ++mt)
#pragma unroll
                for (int np = 0; np < 4; ++np) {
                    mma16816(acc[mt][2 * np],     a[mt], b[np][0], b[np][2]);
                    mma16816(acc[mt][2 * np + 1], a[mt], b[np][1], b[np][3]);
                }
        }
    }

    // epilogue: +bias, ReLU, fp16 store (+ optional fp32 dual store)
#pragma unroll
    for (int nt = 0; nt < 8; ++nt) {
        const int col = n0 + wn * 64 + nt * 8 + 2 * (lane & 3);
        const float b0v = bias[col], b1v = bias[col + 1];
#pragma unroll
        for (int mt = 0; mt < 4; ++mt) {
            const int row = m0 + wm * 64 + mt * 16 + (lane >> 2);
            const float v0 = fmaxf(acc[mt][nt][0] + b0v, 0.f);
            const float v1 = fmaxf(acc[mt][nt][1] + b1v, 0.f);
            const float v2 = fmaxf(acc[mt][nt][2] + b0v, 0.f);
            const float v3 = fmaxf(acc[mt][nt][3] + b1v, 0.f);
            const size_t o0 = (size_t)row * N + col;
            const size_t o1 = (size_t)(row + 8) * N + col;
            if (DUAL) {
                *(float2*)(C2 + o0) = make_float2(v0, v1);
                *(float2*)(C2 + o1) = make_float2(v2, v3);
            }
            *(__half2*)(C + o0) = __floats2half2_rn(v0, v1);
            *(__half2*)(C + o1) = __floats2half2_rn(v2, v3);
        }
    }
}

// ---------------------------------------------------------------------------
// Head: per compact slot s (< cnt): y[idx[s]] = dot(G1[s,:512], Wo) + bo,
// t_out[idx[s]] = 1 (softmax over size-1 axis). G1 is fp16.
// ---------------------------------------------------------------------------
__global__ void head_kernel(const int* __restrict__ idx,
                            const int* __restrict__ cnt_ptr,
                            const __half* __restrict__ G1,
                            const float* __restrict__ Wo,
                            const float* __restrict__ bo,
                            float* __restrict__ y, float* __restrict__ tout) {
    const int cnt = __ldg(cnt_ptr);
    const int slot = blockIdx.x * 8 + (threadIdx.x >> 5);
    if (slot >= cnt) return;
    const int lane = threadIdx.x & 31;
    const __half* g = G1 + (size_t)slot * 512;
    float s = 0.f;
#pragma unroll
    for (int j = 0; j < 2; j++) {
        const int base = j * 256 + lane * 8;
        uint4 gv = *(const uint4*)(g + base);
        float4 w0 = *(const float4*)(Wo + base);
        float4 w1 = *(const float4*)(Wo + base + 4);
        float2 f0 = __half22float2(*(__half2*)&gv.x);
        float2 f1 = __half22float2(*(__half2*)&gv.y);
        float2 f2 = __half22float2(*(__half2*)&gv.z);
        float2 f3 = __half22float2(*(__half2*)&gv.w);
        s += f0.x * w0.x + f0.y * w0.y + f1.x * w0.z + f1.y * w0.w;
        s += f2.x * w1.x + f2.y * w1.y + f3.x * w1.z + f3.y * w1.w;
    }
#pragma unroll
    for (int o = 16; o > 0; o >>= 1) s += __shfl_xor_sync(0xffffffffu, s, o);
    if (lane == 0) {
        const int orig = idx[slot];
        y[orig]    = s + bo[0];
        tout[orig] = 1.0f;
    }
}

// ---------------------------------------------------------------------------
extern "C" void kernel_launch(void* const* d_in, const int* in_sizes, int n_in,
                              void* d_out, int out_size) {
    const float* x   = (const float*)d_in[0];
    const int*   tr  = (const int*)  d_in[1];
    const float* Wx0 = (const float*)d_in[2];
    const float* bx0 = (const float*)d_in[3];
    const float* Wx1 = (const float*)d_in[4];
    const float* bx1 = (const float*)d_in[5];
    const float* Wx2 = (const float*)d_in[6];
    const float* bx2 = (const float*)d_in[7];
    const float* Wy0 = (const float*)d_in[8];
    const float* by0 = (const float*)d_in[9];
    const float* Wy1 = (const float*)d_in[10];
    const float* by1 = (const float*)d_in[11];
    const float* Wo  = (const float*)d_in[12];
    const float* bo  = (const float*)d_in[13];
    // Wt/bt dead: softmax over size-1 axis == 1.

    float* out  = (float*)d_out;
    float* y    = out;
    float* xemb = out + NROWS;
    float* tout = out + NROWS + (size_t)NROWS * 512;

    __half* scr = nullptr;
    cudaGetSymbolAddress((void**)&scr, g_scratch);
    int* idx0 = nullptr; cudaGetSymbolAddress((void**)&idx0, g_idx0);
    int* idx1 = nullptr; cudaGetSymbolAddress((void**)&idx1, g_idx1);
    int* meta = nullptr; cudaGetSymbolAddress((void**)&meta, g_meta);

    __half* Xh   = scr + OFF_XH;
    __half* WX0T = scr + OFF_WX0;
    __half* WX1T = scr + OFF_WX1;
    __half* WX2T = scr + OFF_WX2;
    __half* WY0T = scr + OFF_WY0;
    __half* WY1T = scr + OFF_WY1;
    __half* H0   = scr + OFF_H0;
    __half* H1   = scr + OFF_H1;
    __half* XEh  = scr + OFF_XEH;
    __half* G0a  = scr + OFF_G0A;
    __half* G0b  = scr + OFF_G0B;
    __half* G1a  = scr + OFF_G1A;
    __half* G1b  = scr + OFF_G1B;

    cudaFuncSetAttribute(gemm_fp16<false, false, false>,
                         cudaFuncAttributeMaxDynamicSharedMemorySize, GEMM_SMEM);
    cudaFuncSetAttribute(gemm_fp16<true,  false, false>,
                         cudaFuncAttributeMaxDynamicSharedMemorySize, GEMM_SMEM);
    cudaFuncSetAttribute(gemm_fp16<false, true,  true>,
                         cudaFuncAttributeMaxDynamicSharedMemorySize, GEMM_SMEM);
    cudaFuncSetAttribute(gemm_fp16<false, false, true>,
                         cudaFuncAttributeMaxDynamicSharedMemorySize, GEMM_SMEM);

    // prep + partition
    zero_meta_kernel<<<1, 32>>>();
    scatter_kernel<<<NROWS / 256, 256>>>(tr);
    pad_kernel<<<1, 256>>>();
    {
        int n8 = (int)((size_t)NROWS * 512 / 8);
        cvt_half_kernel<<<(n8 + 255) / 256, 256>>>((const float4*)x, Xh, n8);
    }
    prep_transpose<<<TS_TOTAL, dim3(32, 8)>>>(Wx0, Wx1, Wx2, Wy0, Wy1, scr);

    const dim3 blk(256);
    const int MT = NROWS / 256;

    // trunk (dense)
    gemm_fp16<false, false, false><<<dim3(2048 / 128, MT), blk, GEMM_SMEM>>>(
        Xh, WX0T, bx0, H0, nullptr, nullptr, nullptr, 2048, 512);
    gemm_fp16<false, false, false><<<dim3(2048 / 128, MT), blk, GEMM_SMEM>>>(
        H0, WX1T, bx1, H1, nullptr, nullptr, nullptr, 2048, 2048);
    gemm_fp16<true, false, false><<<dim3(512 / 128, MT), blk, GEMM_SMEM>>>(
        H1, WX2T, bx2, XEh, xemb, nullptr, nullptr, 512, 2048);

    // experts (gathered, compact, early-exit past padded count)
    gemm_fp16<false, true, true><<<dim3(1024 / 128, MT), blk, GEMM_SMEM>>>(
        XEh, WY0T, by0, G0a, nullptr, idx0, meta + 1, 1024, 512);
    gemm_fp16<false, true, true><<<dim3(1024 / 128, MT), blk, GEMM_SMEM>>>(
        XEh, WY0T + (size_t)1024 * 512, by0 + 1024, G0b, nullptr, idx1, meta + 3, 1024, 512);
    gemm_fp16<false, false, true><<<dim3(512 / 128, MT), blk, GEMM_SMEM>>>(
        G0a, WY1T, by1, G1a, nullptr, nullptr, meta + 1, 512, 1024);
    gemm_fp16<false, false, true><<<dim3(512 / 128, MT), blk, GEMM_SMEM>>>(
        G0b, WY1T + (size_t)512 * 1024, by1 + 512, G1b, nullptr, nullptr, meta + 3, 512, 1024);

    // gathered heads (scatter y / t_out by original row)
    head_kernel<<<NROWS / 8, 256>>>(idx0, meta + 0, G1a, Wo,       bo,     y, tout);
    head_kernel<<<NROWS / 8, 256>>>(idx1, meta + 2, G1b, Wo + 512, bo + 1, y, tout);
}